// round 16
// baseline (speedup 1.0000x reference)
#include <cuda_runtime.h>
#include <cstdint>

#define C_   8
#define M_   2048
#define D_   2048
#define B_   256
#define CM_  (C_ * M_)
#define KNN  50
#define INVT 20.0f   // 1/TEMP

// ---- scratch (device globals: allocation-free rule) ----
__device__ float g_sims[(size_t)B_ * CM_];   // 16 MB

// ============================================================
// helpers
// ============================================================
__device__ __forceinline__ uint32_t smem_u32(const void* p) {
    uint32_t a;
    asm("{ .reg .u64 t; cvta.to.shared.u64 t, %1; cvt.u32.u64 %0, t; }" : "=r"(a) : "l"(p));
    return a;
}
__device__ __forceinline__ uint32_t pk_bf16(float lo, float hi) {
    uint32_t r;
    asm("cvt.rn.bf16x2.f32 %0, %1, %2;" : "=r"(r) : "f"(hi), "f"(lo));   // d.hi=%1, d.lo=%2
    return r;
}
__device__ __forceinline__ void ldsm_x4(uint32_t& r0, uint32_t& r1, uint32_t& r2, uint32_t& r3,
                                        uint32_t addr) {
    asm volatile("ldmatrix.sync.aligned.m8n8.x4.shared.b16 {%0,%1,%2,%3}, [%4];"
                 : "=r"(r0), "=r"(r1), "=r"(r2), "=r"(r3) : "r"(addr));
}
__device__ __forceinline__ void mma_bf16(float& d0, float& d1, float& d2, float& d3,
                                         uint32_t a0, uint32_t a1, uint32_t a2, uint32_t a3,
                                         uint32_t b0, uint32_t b1) {
    asm volatile(
        "mma.sync.aligned.m16n8k16.row.col.f32.bf16.bf16.f32 "
        "{%0,%1,%2,%3}, {%4,%5,%6,%7}, {%8,%9}, {%0,%1,%2,%3};"
        : "+f"(d0), "+f"(d1), "+f"(d2), "+f"(d3)
        : "r"(a0), "r"(a1), "r"(a2), "r"(a3), "r"(b0), "r"(b1));
}

// ============================================================
// block reduction (width-generic, blockDim multiple of 32)
// ============================================================
__device__ __forceinline__ float blockReduceSum(float val) {
    __shared__ float sh[32];
    int lane = threadIdx.x & 31, wid = threadIdx.x >> 5;
    #pragma unroll
    for (int o = 16; o; o >>= 1) val += __shfl_down_sync(0xffffffffu, val, o);
    if (lane == 0) sh[wid] = val;
    __syncthreads();
    int nw = (blockDim.x + 31) >> 5;
    val = (threadIdx.x < (unsigned)nw) ? sh[threadIdx.x] : 0.f;
    if (wid == 0) {
        #pragma unroll
        for (int o = 16; o; o >>= 1) val += __shfl_down_sync(0xffffffffu, val, o);
        if (lane == 0) sh[0] = val;
    }
    __syncthreads();
    val = sh[0];
    __syncthreads();
    return val;
}
__device__ __forceinline__ unsigned fkey(float f) {
    unsigned u = __float_as_uint(f);
    return (u & 0x80000000u) ? ~u : (u | 0x80000000u);
}
__device__ __forceinline__ float fkeyinv(unsigned k) {
    unsigned u = (k & 0x80000000u) ? (k & 0x7FFFFFFFu) : ~k;
    return __uint_as_float(u);
}

// ============================================================
// 1) bf16 mma.sync GEMM + fused em copy.
//    CTA tile 256(M) x 128(N), grid 128 (one CTA/SM, single wave),
//    512 threads, 16 warps (4x4), warp tile 64x32, BK=32.
//    Inner loop: batch all 6 LDSMs per k16-step, then 32 MMAs (ILP).
//    em copied through registers (scalar stores; out+1 is 4B-aligned).
//    Zeroes out[0] (loss accumulator) each launch.
// ============================================================
#define BK      32
#define NCHUNK  (D_ / BK)                 // 64
#define BSTRIDE 20                        // uints per bf16 tile row (16 + 4 pad)
#define ATILE_U (256 * BSTRIDE)           // 5120 uints
#define BTILE_U (128 * BSTRIDE)           // 2560 uints
#define BUF_U   (ATILE_U + BTILE_U)       // 7680 uints per buffer
#define GEMM_SMEM (2 * BUF_U * 4)         // 61440 B

__global__ void __launch_bounds__(512, 1) gemm_mma_kernel(const float* __restrict__ inp,
                                                          const float* __restrict__ em,
                                                          float* __restrict__ out) {
    extern __shared__ uint32_t smem[];    // [buf0: A,B][buf1: A,B]
    const int tid  = threadIdx.x;
    const int lane = tid & 31;
    const int wid  = tid >> 5;
    const int wm   = wid >> 2;            // 0..3 -> 64 M rows each
    const int wn   = wid & 3;             // 0..3 -> 32 N cols each
    const int bn   = blockIdx.x * 128;

    float* out_em = out + 1;
    if (blockIdx.x == 0 && tid == 0) out[0] = 0.f;

    const uint32_t sb = smem_u32(smem);

    // per-thread load mapping: r0 = tid>>3 (0..63), seg s = tid&7
    const int r0 = tid >> 3;
    const int s  = tid & 7;
    const float* gA0 = inp + (size_t)r0 * D_ + s * 4;            // rows r0 + i*64, i=0..3
    const float* gB0 = em  + (size_t)(bn + r0) * D_ + s * 4;     // rows r0 + i*64, i=0..1
    float*       oe0 = out_em + (size_t)(bn + r0) * D_ + s * 4;
    const int soff0 = r0 * BSTRIDE + s * 2;                      // uint index in tile

    // per-lane ldmatrix offsets (byte)
    const int lrow  = (lane & 7) + ((lane >> 3) & 1) * 8;        // 0..15
    const int lcolu = ((lane >> 4) & 1) * 4;                     // 0 or 4 uints
    const uint32_t aoff = (uint32_t)(((wm * 64 + lrow) * BSTRIDE + lcolu) * 4);
    const uint32_t boff = (uint32_t)(((wn * 32 + lrow) * BSTRIDE + lcolu) * 4);

    float acc[4][4][4];
    #pragma unroll
    for (int mi = 0; mi < 4; mi++)
        #pragma unroll
        for (int ni = 0; ni < 4; ni++)
            #pragma unroll
            for (int j = 0; j < 4; j++) acc[mi][ni][j] = 0.f;

    float4 curA[4], curB[2];
    #pragma unroll
    for (int i = 0; i < 4; i++) curA[i] = __ldg((const float4*)(gA0 + (size_t)i * 64 * D_));
    #pragma unroll
    for (int i = 0; i < 2; i++) curB[i] = __ldg((const float4*)(gB0 + (size_t)i * 64 * D_));

    for (int k = 0; k < NCHUNK; k++) {
        const int buf = k & 1;
        uint32_t* Ab = smem + buf * BUF_U;
        uint32_t* Bb = Ab + ATILE_U;
        const int k0 = k * BK;

        // convert chunk k to bf16 tiles; em write-through (scalar stores)
        #pragma unroll
        for (int i = 0; i < 4; i++) {
            const int so = soff0 + i * (64 * BSTRIDE);
            *(uint2*)(Ab + so) = make_uint2(pk_bf16(curA[i].x, curA[i].y), pk_bf16(curA[i].z, curA[i].w));
        }
        #pragma unroll
        for (int i = 0; i < 2; i++) {
            const int so = soff0 + i * (64 * BSTRIDE);
            float* d = oe0 + (size_t)i * 64 * D_ + k0;
            d[0] = curB[i].x; d[1] = curB[i].y; d[2] = curB[i].z; d[3] = curB[i].w;
            *(uint2*)(Bb + so) = make_uint2(pk_bf16(curB[i].x, curB[i].y), pk_bf16(curB[i].z, curB[i].w));
        }
        __syncthreads();

        // prefetch chunk k+1 into regs
        if (k + 1 < NCHUNK) {
            const float* pa = gA0 + (k + 1) * BK;
            const float* pb = gB0 + (k + 1) * BK;
            #pragma unroll
            for (int i = 0; i < 4; i++) curA[i] = __ldg((const float4*)(pa + (size_t)i * 64 * D_));
            #pragma unroll
            for (int i = 0; i < 2; i++) curB[i] = __ldg((const float4*)(pb + (size_t)i * 64 * D_));
        }

        // fragments via ldmatrix (all 6 LDSM batched), then 32 MMAs per k16
        const uint32_t base  = sb + (uint32_t)(buf * BUF_U * 4);
        const uint32_t Abase = base + aoff;
        const uint32_t Bbase = base + (uint32_t)(ATILE_U * 4) + boff;
        #pragma unroll
        for (int kk = 0; kk < 2; kk++) {
            uint32_t bfr[8];
            uint32_t afr[4][4];
            ldsm_x4(bfr[0], bfr[1], bfr[2], bfr[3], Bbase + kk * 32);          // n 0-15
            ldsm_x4(bfr[4], bfr[5], bfr[6], bfr[7], Bbase + 1280 + kk * 32);   // n 16-31
            #pragma unroll
            for (int mi = 0; mi < 4; mi++)
                ldsm_x4(afr[mi][0], afr[mi][1], afr[mi][2], afr[mi][3],
                        Abase + mi * 1280 + kk * 32);
            #pragma unroll
            for (int mi = 0; mi < 4; mi++) {
                mma_bf16(acc[mi][0][0], acc[mi][0][1], acc[mi][0][2], acc[mi][0][3],
                         afr[mi][0], afr[mi][1], afr[mi][2], afr[mi][3], bfr[0], bfr[2]);
                mma_bf16(acc[mi][1][0], acc[mi][1][1], acc[mi][1][2], acc[mi][1][3],
                         afr[mi][0], afr[mi][1], afr[mi][2], afr[mi][3], bfr[1], bfr[3]);
                mma_bf16(acc[mi][2][0], acc[mi][2][1], acc[mi][2][2], acc[mi][2][3],
                         afr[mi][0], afr[mi][1], afr[mi][2], afr[mi][3], bfr[4], bfr[6]);
                mma_bf16(acc[mi][3][0], acc[mi][3][1], acc[mi][3][2], acc[mi][3][3],
                         afr[mi][0], afr[mi][1], afr[mi][2], afr[mi][3], bfr[5], bfr[7]);
            }
        }
        // next STS targets the other buffer; this chunk's bar already ordered it.
    }

    // epilogue (g_sims 16B-aligned: float2 OK)
    #pragma unroll
    for (int mi = 0; mi < 4; mi++) {
        const int rr = wm * 64 + mi * 16 + (lane >> 2);
        #pragma unroll
        for (int ni = 0; ni < 4; ni++) {
            const int c = bn + wn * 32 + ni * 8 + (lane & 3) * 2;
            *(float2*)(g_sims + (size_t)rr * CM_ + c)       = make_float2(acc[mi][ni][0], acc[mi][ni][1]);
            *(float2*)(g_sims + (size_t)(rr + 8) * CM_ + c) = make_float2(acc[mi][ni][2], acc[mi][ni][3]);
        }
    }
}

// ============================================================
// 2) fused loss + EMA + final reduction (512 threads/block).
//    Key exactness fact: |sims| <= 1 (unit-norm rows, Cauchy-Schwarz)
//    -> exp(v*INVT) <= e^20 ~ 4.9e8, all sums < 1e12: fp32-safe with
//    NO max-shift anywhere. All max passes/reductions removed.
//    Top-50: fused count+compact at t = mu+2.4*sigma (CAP=512, one
//    candidate key per thread); count ops via __syncthreads_count.
//    Adaptive re-threshold + exact full binary search as fallbacks.
// ============================================================
#define NT    512
#define CAPK  512
#define LOSS_SMEM (CM_ * 4 + CAPK * 4)

__global__ void __launch_bounds__(NT) loss_ema_kernel(const float* __restrict__ inp,
                                                      const int* __restrict__ targets,
                                                      const int* __restrict__ cams,
                                                      const int* __restrict__ ep,
                                                      float* __restrict__ out) {
    extern __shared__ float srow[];                       // CM_ floats
    unsigned* buf = (unsigned*)(srow + CM_);              // CAPK keys
    __shared__ float spos[C_];
    __shared__ unsigned s_cnt;
    __shared__ int srid[B_];

    const int b = blockIdx.x, tid = threadIdx.x;
    const int target = targets[b], cam = cams[b];
    const float* row = g_sims + (size_t)b * CM_;
    float* em_out = out + 1;

    if (tid == 0) s_cnt = 0;
    if (tid < B_) srid[tid] = cams[tid] * M_ + targets[tid];

    // ---- sweep 1: stage row (mask positives) + sum/sumsq ----
    float lsum = 0.f, lsq = 0.f;
    for (int i = tid; i < CM_; i += NT) {
        float v = row[i];
        if ((i & (M_ - 1)) == target) v = -1000.f;
        srow[i] = v;
        lsum += v;
        lsq  += v * v;
    }
    if (tid < C_) spos[tid] = row[tid * M_ + target];
    __syncthreads();

    float sum = blockReduceSum(lsum) + 8000.f;            // remove 8 masked -1000s
    float sq  = blockReduceSum(lsq) - 8.e6f;
    const float nvalid = (float)(CM_ - C_);
    const float mu  = sum / nvalid;
    const float sig = sqrtf(fmaxf(sq / nvalid - mu * mu, 1e-20f));

    const int cnt = __syncthreads_count(tid < B_ && cams[tid] == cam);

    // ---- intra-camera CE (no max-shift; |v|<=1 so exp(20v) is safe) ----
    float sl = 0.f;
    for (int i = cam * M_ + tid; i < (cam + 1) * M_; i += NT)
        sl += __expf(srow[i] * INVT);                     // masked entry -> 0
    float sce = blockReduceSum(sl);
    sce += __expf(spos[cam] * INVT);
    const float ce = __logf(sce) - spos[cam] * INVT;

    // ---- hard-negative associate loss ----
    int epoch = ep ? ep[0] : 6;
    float al = 0.f;
    if (epoch >= 5) {
        float psum = 0.f;
        #pragma unroll
        for (int c2 = 0; c2 < C_; c2++) psum += spos[c2];

        // fused count+compact at t = mu + 2.4*sigma (expected ~134 cands)
        float t = mu + 2.4f * sig;
        for (int i = tid; i < CM_; i += NT) {
            float v = srow[i];
            if (v >= t) { unsigned p = atomicAdd(&s_cnt, 1u); if (p < CAPK) buf[p] = fkey(v); }
        }
        __syncthreads();
        unsigned S = s_cnt;
        bool ok = (S >= (unsigned)KNN && S <= (unsigned)CAPK);

        if (!ok) {
            // adaptive count-only loop, then recompact
            float z = 2.4f;
            for (int it = 0; it < 8 && !ok; it++) {
                z += (S < (unsigned)KNN) ? -0.5f : 0.45f;
                t = mu + z * sig;
                float c = 0.f;
                for (int i = tid; i < CM_; i += NT) c += (srow[i] >= t) ? 1.f : 0.f;
                c = blockReduceSum(c);
                S = (unsigned)(c + 0.5f);
                ok = (S >= (unsigned)KNN && S <= (unsigned)CAPK);
            }
            if (ok) {
                if (tid == 0) s_cnt = 0;
                __syncthreads();
                for (int i = tid; i < CM_; i += NT) {
                    float v = srow[i];
                    if (v >= t) { unsigned p = atomicAdd(&s_cnt, 1u); buf[p] = fkey(v); }
                }
                __syncthreads();
                S = s_cnt;
            }
        }

        unsigned k50;
        float cg, sn;
        if (ok) {
            // one candidate key per thread; all counts via HW barrier-popcount
            const unsigned kreg = (tid < (int)S) ? buf[tid] : 0u;
            unsigned lo = fkey(t), hi = fkey(1.05f);      // |sims| <= ~1.01 incl. bf16 noise
            while (lo < hi) {
                unsigned mid = lo + ((hi - lo + 1u) >> 1);
                int c = __syncthreads_count(kreg >= mid);
                if (c >= KNN) lo = mid; else hi = mid - 1u;
            }
            k50 = lo;
            cg = (float)__syncthreads_count(kreg > k50);
            sn = blockReduceSum((kreg > k50) ? __expf(fkeyinv(kreg) * INVT) : 0.f);
        } else {
            // exact fallback: full-key binary search over the whole row
            unsigned lo = 0u, hi = fkey(1.05f);
            while (lo < hi) {
                unsigned mid = lo + ((hi - lo + 1u) >> 1);
                float c = 0.f;
                for (int i = tid; i < CM_; i += NT)
                    c += (fkey(srow[i]) >= mid) ? 1.f : 0.f;
                c = blockReduceSum(c);
                if (c >= (float)KNN) lo = mid; else hi = mid - 1u;
            }
            k50 = lo;
            float cgl = 0.f, snl = 0.f;
            for (int i = tid; i < CM_; i += NT) {
                float v = srow[i];
                if (fkey(v) > k50) { cgl += 1.f; snl += __expf(v * INVT); }
            }
            cg = blockReduceSum(cgl);
            sn = blockReduceSum(snl);
        }

        const float v50 = fkeyinv(k50);
        sn += ((float)KNN - cg) * __expf(v50 * INVT);      // tie-correct

        float sp = 0.f;
        #pragma unroll
        for (int c2 = 0; c2 < C_; c2++) sp += __expf(spos[c2] * INVT);
        const float lse = __logf(sp + sn);
        al = lse - psum * INVT / (float)C_;
    }

    if (tid == 0) atomicAdd(out, (ce + 0.5f * al) / (float)cnt);

    // ---- fused EMA scatter + renorm (block-uniform ownership) ----
    __syncthreads();                       // srid visible
    const int r = srid[b];
    bool owner = true;
    for (int bp = 0; bp < b; bp++)
        if (srid[bp] == r) { owner = false; break; }
    if (!owner) return;

    float v[4];
    const size_t base = (size_t)r * D_ + tid * 4;
    #pragma unroll
    for (int j = 0; j < 4; j++) v[j] = em_out[base + j];

    for (int bb = b; bb < B_; bb++) {
        if (srid[bb] != r) continue;       // uniform across block
        float4 x = *(const float4*)(inp + (size_t)bb * D_ + tid * 4);
        float xv[4] = {x.x, x.y, x.z, x.w};
        float ss = 0.f;
        #pragma unroll
        for (int j = 0; j < 4; j++) {
            v[j] = 0.2f * v[j] + 0.8f * xv[j];
            ss += v[j] * v[j];
        }
        ss = blockReduceSum(ss);
        float inv = rsqrtf(ss);
        #pragma unroll
        for (int j = 0; j < 4; j++) v[j] *= inv;
    }
    #pragma unroll
    for (int j = 0; j < 4; j++) em_out[base + j] = v[j];
}

// ============================================================
extern "C" void kernel_launch(void* const* d_in, const int* in_sizes, int n_in,
                              void* d_out, int out_size) {
    const float* inp     = (const float*)d_in[0];
    const float* em      = (const float*)d_in[1];
    const int*   targets = (const int*)d_in[2];
    const int*   cams    = (const int*)d_in[3];
    const int*   ep      = (n_in >= 5) ? (const int*)d_in[4] : nullptr;
    float* out = (float*)d_out;

    cudaFuncSetAttribute(loss_ema_kernel, cudaFuncAttributeMaxDynamicSharedMemorySize, LOSS_SMEM);
    cudaFuncSetAttribute(gemm_mma_kernel, cudaFuncAttributeMaxDynamicSharedMemorySize, GEMM_SMEM);

    gemm_mma_kernel<<<CM_ / 128, 512, GEMM_SMEM>>>(inp, em, out);
    loss_ema_kernel<<<B_, NT, LOSS_SMEM>>>(inp, targets, cams, ep, out);
}

// round 17
// speedup vs baseline: 1.3851x; 1.3851x over previous
#include <cuda_runtime.h>
#include <cstdint>

#define C_   8
#define M_   2048
#define D_   2048
#define B_   256
#define CM_  (C_ * M_)
#define KNN  50
#define INVT 20.0f   // 1/TEMP

// ---- scratch (device globals: allocation-free rule) ----
__device__ float g_sims[(size_t)B_ * CM_];   // 16 MB

// ============================================================
// helpers
// ============================================================
__device__ __forceinline__ uint32_t smem_u32(const void* p) {
    uint32_t a;
    asm("{ .reg .u64 t; cvta.to.shared.u64 t, %1; cvt.u32.u64 %0, t; }" : "=r"(a) : "l"(p));
    return a;
}
__device__ __forceinline__ uint32_t pk_bf16(float lo, float hi) {
    uint32_t r;
    asm("cvt.rn.bf16x2.f32 %0, %1, %2;" : "=r"(r) : "f"(hi), "f"(lo));   // d.hi=%1, d.lo=%2
    return r;
}
__device__ __forceinline__ void ldsm_x4(uint32_t& r0, uint32_t& r1, uint32_t& r2, uint32_t& r3,
                                        uint32_t addr) {
    asm volatile("ldmatrix.sync.aligned.m8n8.x4.shared.b16 {%0,%1,%2,%3}, [%4];"
                 : "=r"(r0), "=r"(r1), "=r"(r2), "=r"(r3) : "r"(addr));
}
__device__ __forceinline__ void mma_bf16(float& d0, float& d1, float& d2, float& d3,
                                         uint32_t a0, uint32_t a1, uint32_t a2, uint32_t a3,
                                         uint32_t b0, uint32_t b1) {
    asm volatile(
        "mma.sync.aligned.m16n8k16.row.col.f32.bf16.bf16.f32 "
        "{%0,%1,%2,%3}, {%4,%5,%6,%7}, {%8,%9}, {%0,%1,%2,%3};"
        : "+f"(d0), "+f"(d1), "+f"(d2), "+f"(d3)
        : "r"(a0), "r"(a1), "r"(a2), "r"(a3), "r"(b0), "r"(b1));
}

// ============================================================
// block reduction (width-generic, blockDim multiple of 32)
// ============================================================
__device__ __forceinline__ float blockReduceSum(float val) {
    __shared__ float sh[32];
    int lane = threadIdx.x & 31, wid = threadIdx.x >> 5;
    #pragma unroll
    for (int o = 16; o; o >>= 1) val += __shfl_down_sync(0xffffffffu, val, o);
    if (lane == 0) sh[wid] = val;
    __syncthreads();
    int nw = (blockDim.x + 31) >> 5;
    val = (threadIdx.x < (unsigned)nw) ? sh[threadIdx.x] : 0.f;
    if (wid == 0) {
        #pragma unroll
        for (int o = 16; o; o >>= 1) val += __shfl_down_sync(0xffffffffu, val, o);
        if (lane == 0) sh[0] = val;
    }
    __syncthreads();
    val = sh[0];
    __syncthreads();
    return val;
}
__device__ __forceinline__ unsigned fkey(float f) {
    unsigned u = __float_as_uint(f);
    return (u & 0x80000000u) ? ~u : (u | 0x80000000u);
}
__device__ __forceinline__ float fkeyinv(unsigned k) {
    unsigned u = (k & 0x80000000u) ? (k & 0x7FFFFFFFu) : ~k;
    return __uint_as_float(u);
}

// ============================================================
// 1) bf16 mma.sync GEMM + fused em copy (round-12 proven config).
//    CTA 128x128, 256 threads, 8 warps (2x4), warp tile 64x32, BK=32.
//    LDG fp32 -> reg bf16 convert -> double-buffered smem tiles,
//    ldmatrix fragments (per-mi, unbatched), one syncthreads per chunk.
//    B-tile write-through to out_em with scalar stores (out+1 is 4B-aligned).
//    Zeroes out[0] (loss accumulator) each launch.
// ============================================================
#define BK      32
#define NCHUNK  (D_ / BK)                 // 64
#define BSTRIDE 20                        // uints per bf16 tile row (16 + 4 pad)
#define BTILE_U (128 * BSTRIDE)           // 2560 uints = 10240 B
#define GEMM_SMEM (4 * BTILE_U * 4)       // 40960 B

__global__ void __launch_bounds__(256, 2) gemm_mma_kernel(const float* __restrict__ inp,
                                                          const float* __restrict__ em,
                                                          float* __restrict__ out) {
    extern __shared__ uint32_t smem[];    // [buf0:A,B][buf1:A,B]
    const int tid  = threadIdx.x;
    const int lane = tid & 31;
    const int wid  = tid >> 5;
    const int wm   = wid >> 2;            // 0..1 -> 64 M rows
    const int wn   = wid & 3;             // 0..3 -> 32 N cols
    const int bm   = blockIdx.y * 128;
    const int bmid = blockIdx.y;          // 0 or 1
    const int bn   = blockIdx.x * 128;

    float* out_em = out + 1;
    if (blockIdx.x == 0 && blockIdx.y == 0 && tid == 0) out[0] = 0.f;

    const uint32_t sb = smem_u32(smem);

    // per-thread load mapping: r0 = tid>>3 (0..31), seg s = tid&7
    const int r0 = tid >> 3;
    const int s  = tid & 7;
    const float* gA0 = inp + (size_t)(bm + r0) * D_ + s * 4;
    const float* gB0 = em  + (size_t)(bn + r0) * D_ + s * 4;
    float*       oe0 = out_em + (size_t)(bn + r0) * D_ + s * 4;
    const int soff0 = r0 * BSTRIDE + s * 2;          // uint index in tile

    // per-lane ldmatrix offsets (byte)
    const int lrow  = (lane & 7) + ((lane >> 3) & 1) * 8;   // 0..15
    const int lcolu = ((lane >> 4) & 1) * 4;                // 0 or 4 uints
    const uint32_t aoff = (uint32_t)(((wm * 64 + lrow) * BSTRIDE + lcolu) * 4);
    const uint32_t boff = (uint32_t)(((wn * 32 + lrow) * BSTRIDE + lcolu) * 4);

    float acc[4][4][4];
    #pragma unroll
    for (int mi = 0; mi < 4; mi++)
        #pragma unroll
        for (int ni = 0; ni < 4; ni++)
            #pragma unroll
            for (int j = 0; j < 4; j++) acc[mi][ni][j] = 0.f;

    float4 curA[4], curB[4];
    #pragma unroll
    for (int i = 0; i < 4; i++) {
        curA[i] = __ldg((const float4*)(gA0 + (size_t)i * 32 * D_));
        curB[i] = __ldg((const float4*)(gB0 + (size_t)i * 32 * D_));
    }

    for (int k = 0; k < NCHUNK; k++) {
        const int buf = k & 1;
        uint32_t* Ab = smem + buf * 2 * BTILE_U;
        uint32_t* Bb = Ab + BTILE_U;
        const bool do_copy = ((k >> 5) == bmid);
        const int k0 = k * BK;

        // convert chunk k to bf16 tiles (+ scalar write-through em copy)
        #pragma unroll
        for (int i = 0; i < 4; i++) {
            const int so = soff0 + i * (32 * BSTRIDE);
            if (do_copy) {
                float* d = oe0 + (size_t)i * 32 * D_ + k0;
                d[0] = curB[i].x; d[1] = curB[i].y; d[2] = curB[i].z; d[3] = curB[i].w;
            }
            *(uint2*)(Ab + so) = make_uint2(pk_bf16(curA[i].x, curA[i].y), pk_bf16(curA[i].z, curA[i].w));
            *(uint2*)(Bb + so) = make_uint2(pk_bf16(curB[i].x, curB[i].y), pk_bf16(curB[i].z, curB[i].w));
        }
        __syncthreads();

        // prefetch chunk k+1 into regs
        if (k + 1 < NCHUNK) {
            const float* pa = gA0 + (k + 1) * BK;
            const float* pb = gB0 + (k + 1) * BK;
            #pragma unroll
            for (int i = 0; i < 4; i++) {
                curA[i] = __ldg((const float4*)(pa + (size_t)i * 32 * D_));
                curB[i] = __ldg((const float4*)(pb + (size_t)i * 32 * D_));
            }
        }

        // fragments via ldmatrix + MMA (unbatched: keeps regs under the cliff)
        const uint32_t Abase = sb + (uint32_t)(buf * 2 * BTILE_U * 4) + aoff;
        const uint32_t Bbase = sb + (uint32_t)(buf * 2 * BTILE_U * 4) + (uint32_t)(BTILE_U * 4) + boff;
        #pragma unroll
        for (int kk = 0; kk < 2; kk++) {
            uint32_t b0, b1, b2, b3, b4, b5, b6, b7;
            ldsm_x4(b0, b1, b2, b3, Bbase + kk * 32);            // n 0-15 of warp tile
            ldsm_x4(b4, b5, b6, b7, Bbase + 1280 + kk * 32);     // n 16-31
            #pragma unroll
            for (int mi = 0; mi < 4; mi++) {
                uint32_t a0, a1, a2, a3;
                ldsm_x4(a0, a1, a2, a3, Abase + mi * 1280 + kk * 32);
                mma_bf16(acc[mi][0][0], acc[mi][0][1], acc[mi][0][2], acc[mi][0][3],
                         a0, a1, a2, a3, b0, b2);
                mma_bf16(acc[mi][1][0], acc[mi][1][1], acc[mi][1][2], acc[mi][1][3],
                         a0, a1, a2, a3, b1, b3);
                mma_bf16(acc[mi][2][0], acc[mi][2][1], acc[mi][2][2], acc[mi][2][3],
                         a0, a1, a2, a3, b4, b6);
                mma_bf16(acc[mi][3][0], acc[mi][3][1], acc[mi][3][2], acc[mi][3][3],
                         a0, a1, a2, a3, b5, b7);
            }
        }
        // next STS targets the other buffer; this chunk's bar already ordered it.
    }

    // epilogue (g_sims 16B-aligned: float2 OK)
    #pragma unroll
    for (int mi = 0; mi < 4; mi++) {
        const int rr = bm + wm * 64 + mi * 16 + (lane >> 2);
        #pragma unroll
        for (int ni = 0; ni < 4; ni++) {
            const int c = bn + wn * 32 + ni * 8 + (lane & 3) * 2;
            *(float2*)(g_sims + (size_t)rr * CM_ + c)       = make_float2(acc[mi][ni][0], acc[mi][ni][1]);
            *(float2*)(g_sims + (size_t)(rr + 8) * CM_ + c) = make_float2(acc[mi][ni][2], acc[mi][ni][3]);
        }
    }
}

// ============================================================
// 2) fused loss + EMA + final reduction (512 threads/block).
//    Exactness fact: |sims| <= 1 (unit-norm rows) -> exp(20v) <= e^20,
//    sums < 1.2e12: fp32-safe with NO max-shift. All max passes removed.
//    Top-50: statistical threshold (mu+2.4*sigma) count+compact as in the
//    proven round-12 path; 50th-key selection done by WARP 0 ONLY over the
//    compacted candidates (no block barriers in the search loop).
//    Block b atomically adds its loss term to out[0] (zeroed by gemm).
//    EMA: block b owns its row chain if b is the first occurrence.
// ============================================================
#define NT    512
#define CAP   768
#define LOSS_SMEM (CM_ * 4 + CAP * 4)

__global__ void __launch_bounds__(NT) loss_ema_kernel(const float* __restrict__ inp,
                                                      const int* __restrict__ targets,
                                                      const int* __restrict__ cams,
                                                      const int* __restrict__ ep,
                                                      float* __restrict__ out) {
    extern __shared__ float srow[];                       // CM_ floats
    unsigned* buf = (unsigned*)(srow + CM_);              // CAP keys
    __shared__ float spos[C_];
    __shared__ unsigned s_cnt;
    __shared__ unsigned s_k50;
    __shared__ int srid[B_];

    const int b = blockIdx.x, tid = threadIdx.x;
    const int lane = tid & 31, wid = tid >> 5;
    const int target = targets[b], cam = cams[b];
    const float* row = g_sims + (size_t)b * CM_;
    float* em_out = out + 1;

    if (tid == 0) s_cnt = 0;
    if (tid < B_) srid[tid] = cams[tid] * M_ + targets[tid];

    // ---- sweep 1: stage row (mask positives) + sum/sumsq ----
    float lsum = 0.f, lsq = 0.f;
    for (int i = tid; i < CM_; i += NT) {
        float v = row[i];
        if ((i & (M_ - 1)) == target) v = -1000.f;
        srow[i] = v;
        lsum += v;
        lsq  += v * v;
    }
    if (tid < C_) spos[tid] = row[tid * M_ + target];
    __syncthreads();

    float sum = blockReduceSum(lsum) + 8000.f;            // remove 8 masked -1000s
    float sq  = blockReduceSum(lsq) - 8.e6f;
    const float nvalid = (float)(CM_ - C_);
    const float mu  = sum / nvalid;
    const float sig = sqrtf(fmaxf(sq / nvalid - mu * mu, 1e-20f));

    const int cnt = __syncthreads_count(tid < B_ && cams[tid] == cam);

    // ---- intra-camera CE (no max-shift) ----
    float sl = 0.f;
    for (int i = cam * M_ + tid; i < (cam + 1) * M_; i += NT)
        sl += __expf(srow[i] * INVT);                     // masked entry underflows to 0
    float sce = blockReduceSum(sl);
    sce += __expf(spos[cam] * INVT);
    const float ce = __logf(sce) - spos[cam] * INVT;

    // ---- hard-negative associate loss ----
    int epoch = ep ? ep[0] : 6;
    float al = 0.f;
    if (epoch >= 5) {
        float psum = 0.f;
        #pragma unroll
        for (int c2 = 0; c2 < C_; c2++) psum += spos[c2];

        // adaptive threshold: expect ~134 candidates at z=2.4 (round-12 proven)
        float z = 2.4f, t = mu + z * sig;
        bool ok = false;
        for (int it = 0; it < 8; it++) {
            float c = 0.f;
            for (int i = tid; i < CM_; i += NT) c += (srow[i] >= t) ? 1.f : 0.f;
            c = blockReduceSum(c);
            if (c >= (float)KNN && c <= (float)CAP) { ok = true; break; }
            if (c < (float)KNN) z -= 0.5f; else z += 0.45f;
            t = mu + z * sig;
        }

        unsigned k50;
        float cg, sn;
        if (ok) {
            for (int i = tid; i < CM_; i += NT) {
                float v = srow[i];
                if (v >= t) { unsigned p = atomicAdd(&s_cnt, 1u); buf[p] = fkey(v); }
            }
            __syncthreads();
            const int S = (int)s_cnt;

            // 50th-largest key: warp 0 only (no block barriers in the loop)
            if (wid == 0) {
                unsigned lo = fkey(t), hi = fkey(1.05f);
                while (lo < hi) {
                    unsigned mid = lo + ((hi - lo + 1u) >> 1);
                    int c = 0;
                    for (int i = lane; i < S; i += 32) c += (buf[i] >= mid) ? 1 : 0;
                    c = __reduce_add_sync(0xffffffffu, c);
                    if (c >= KNN) lo = mid; else hi = mid - 1u;
                }
                if (lane == 0) s_k50 = lo;
            }
            __syncthreads();
            k50 = s_k50;

            float cgl = 0.f, snl = 0.f;
            for (int i = tid; i < S; i += NT) {
                unsigned kk = buf[i];
                if (kk > k50) { cgl += 1.f; snl += __expf(fkeyinv(kk) * INVT); }
            }
            cg = blockReduceSum(cgl);
            sn = blockReduceSum(snl);
        } else {
            // exact fallback: full-key binary search over the whole row
            unsigned lo = 0u, hi = fkey(1.05f);
            while (lo < hi) {
                unsigned mid = lo + ((hi - lo + 1u) >> 1);
                float c = 0.f;
                for (int i = tid; i < CM_; i += NT)
                    c += (fkey(srow[i]) >= mid) ? 1.f : 0.f;
                c = blockReduceSum(c);
                if (c >= (float)KNN) lo = mid; else hi = mid - 1u;
            }
            k50 = lo;
            float cgl = 0.f, snl = 0.f;
            for (int i = tid; i < CM_; i += NT) {
                float v = srow[i];
                if (fkey(v) > k50) { cgl += 1.f; snl += __expf(v * INVT); }
            }
            cg = blockReduceSum(cgl);
            sn = blockReduceSum(snl);
        }

        const float v50 = fkeyinv(k50);
        sn += ((float)KNN - cg) * __expf(v50 * INVT);      // tie-correct

        float sp = 0.f;
        #pragma unroll
        for (int c2 = 0; c2 < C_; c2++) sp += __expf(spos[c2] * INVT);
        const float lse = __logf(sp + sn);
        al = lse - psum * INVT / (float)C_;
    }

    if (tid == 0) atomicAdd(out, (ce + 0.5f * al) / (float)cnt);

    // ---- fused EMA scatter + renorm (block-uniform ownership) ----
    __syncthreads();                       // srid visible
    const int r = srid[b];
    bool owner = true;
    for (int bp = 0; bp < b; bp++)
        if (srid[bp] == r) { owner = false; break; }
    if (!owner) return;

    float v[4];
    const size_t base = (size_t)r * D_ + tid * 4;
    #pragma unroll
    for (int j = 0; j < 4; j++) v[j] = em_out[base + j];

    for (int bb = b; bb < B_; bb++) {
        if (srid[bb] != r) continue;       // uniform across block
        float4 x = *(const float4*)(inp + (size_t)bb * D_ + tid * 4);
        float xv[4] = {x.x, x.y, x.z, x.w};
        float ss = 0.f;
        #pragma unroll
        for (int j = 0; j < 4; j++) {
            v[j] = 0.2f * v[j] + 0.8f * xv[j];
            ss += v[j] * v[j];
        }
        ss = blockReduceSum(ss);
        float inv = rsqrtf(ss);
        #pragma unroll
        for (int j = 0; j < 4; j++) v[j] *= inv;
    }
    #pragma unroll
    for (int j = 0; j < 4; j++) em_out[base + j] = v[j];
}

// ============================================================
extern "C" void kernel_launch(void* const* d_in, const int* in_sizes, int n_in,
                              void* d_out, int out_size) {
    const float* inp     = (const float*)d_in[0];
    const float* em      = (const float*)d_in[1];
    const int*   targets = (const int*)d_in[2];
    const int*   cams    = (const int*)d_in[3];
    const int*   ep      = (n_in >= 5) ? (const int*)d_in[4] : nullptr;
    float* out = (float*)d_out;

    cudaFuncSetAttribute(loss_ema_kernel, cudaFuncAttributeMaxDynamicSharedMemorySize, LOSS_SMEM);
    cudaFuncSetAttribute(gemm_mma_kernel, cudaFuncAttributeMaxDynamicSharedMemorySize, GEMM_SMEM);

    dim3 gg(CM_ / 128, B_ / 128);
    gemm_mma_kernel<<<gg, 256, GEMM_SMEM>>>(inp, em, out);
    loss_ema_kernel<<<B_, NT, LOSS_SMEM>>>(inp, targets, cams, ep, out);
}